// round 14
// baseline (speedup 1.0000x reference)
#include <cuda_runtime.h>
#include <cuda_bf16.h>
#include <cstdint>
#include <math.h>

#define EPS 1e-6f
constexpr int B = 2, P = 2048, D = 768, H = 12, HD = 64;
constexpr int TOK = B * P;        // 4096
constexpr int QKVN = 3 * D;       // 2304
constexpr int KVS = 2;            // KV splits for attention

// ---------------- scratch (static device globals; no allocation) ----------------
__device__ float g_attp[KVS * TOK * D];   // unnormalized partial attention out
__device__ float2 g_ml[KVS * B * H * P];  // per-row (max, denom)

// split-bf16 operands
__device__ __nv_bfloat16 g_xh[TOK * D];
__device__ __nv_bfloat16 g_xl[TOK * D];
__device__ __nv_bfloat16 g_wqh[QKVN * D];
__device__ __nv_bfloat16 g_wql[QKVN * D];
__device__ __nv_bfloat16 g_woh[D * D];
__device__ __nv_bfloat16 g_wol[D * D];
__device__ __nv_bfloat16 g_a2h[TOK * D];
__device__ __nv_bfloat16 g_a2l[TOK * D];
// attention operands, [bh][p][hd] bf16 hi/lo
__device__ __nv_bfloat16 g_qh[B * H * P * HD];
__device__ __nv_bfloat16 g_ql[B * H * P * HD];
__device__ __nv_bfloat16 g_kh[B * H * P * HD];
__device__ __nv_bfloat16 g_kl[B * H * P * HD];
__device__ __nv_bfloat16 g_vh[B * H * P * HD];
__device__ __nv_bfloat16 g_vl[B * H * P * HD];

// ======================= base-target PTX helpers =======================
__device__ __forceinline__ uint32_t smem_u32(const void* p) {
    uint32_t a;
    asm("{ .reg .u64 t; cvta.to.shared.u64 t, %1; cvt.u32.u64 %0, t; }" : "=r"(a) : "l"(p));
    return a;
}
#define CP_ASYNC16(dst, src) \
    asm volatile("cp.async.cg.shared.global [%0], [%1], 16;" :: "r"(dst), "l"(src))
#define CP_COMMIT() asm volatile("cp.async.commit_group;" ::: "memory")
#define CP_WAIT0()  asm volatile("cp.async.wait_group 0;" ::: "memory")

__device__ __forceinline__ void ldsm_x4(uint32_t& r0, uint32_t& r1, uint32_t& r2,
                                        uint32_t& r3, uint32_t addr) {
    asm volatile("ldmatrix.sync.aligned.m8n8.x4.shared.b16 {%0,%1,%2,%3}, [%4];"
                 : "=r"(r0), "=r"(r1), "=r"(r2), "=r"(r3) : "r"(addr));
}
__device__ __forceinline__ void ldsm_x4_t(uint32_t& r0, uint32_t& r1, uint32_t& r2,
                                          uint32_t& r3, uint32_t addr) {
    asm volatile("ldmatrix.sync.aligned.m8n8.x4.trans.shared.b16 {%0,%1,%2,%3}, [%4];"
                 : "=r"(r0), "=r"(r1), "=r"(r2), "=r"(r3) : "r"(addr));
}
__device__ __forceinline__ void mma16816(float* c, const uint32_t* a, const uint32_t* b) {
    asm volatile(
        "mma.sync.aligned.m16n8k16.row.col.f32.bf16.bf16.f32 "
        "{%0,%1,%2,%3}, {%4,%5,%6,%7}, {%8,%9}, {%0,%1,%2,%3};"
        : "+f"(c[0]), "+f"(c[1]), "+f"(c[2]), "+f"(c[3])
        : "r"(a[0]), "r"(a[1]), "r"(a[2]), "r"(a[3]), "r"(b[0]), "r"(b[1]));
}

// =========================================================================
// Split fp32 -> bf16 hi/lo, same layout.
// =========================================================================
__global__ __launch_bounds__(256) void conv_split(
    const float* __restrict__ src, __nv_bfloat16* __restrict__ hi,
    __nv_bfloat16* __restrict__ lo, int n4)
{
    int i = blockIdx.x * blockDim.x + threadIdx.x;
    if (i >= n4) return;
    float4 v = ((const float4*)src)[i];
    __nv_bfloat16 h0 = __float2bfloat16(v.x), h1 = __float2bfloat16(v.y);
    __nv_bfloat16 h2 = __float2bfloat16(v.z), h3 = __float2bfloat16(v.w);
    __nv_bfloat162* hp = (__nv_bfloat162*)hi;
    __nv_bfloat162* lp = (__nv_bfloat162*)lo;
    hp[2 * i] = __nv_bfloat162(h0, h1);
    hp[2 * i + 1] = __nv_bfloat162(h2, h3);
    lp[2 * i] = __nv_bfloat162(__float2bfloat16(v.x - __bfloat162float(h0)),
                               __float2bfloat16(v.y - __bfloat162float(h1)));
    lp[2 * i + 1] = __nv_bfloat162(__float2bfloat16(v.z - __bfloat162float(h2)),
                                   __float2bfloat16(v.w - __bfloat162float(h3)));
}

// =========================================================================
// Transpose + split: W[K][N] f32 -> T[N][K] bf16 hi/lo.  32x32 tiles.
// =========================================================================
__global__ __launch_bounds__(256) void conv_wT(
    const float* __restrict__ W, __nv_bfloat16* __restrict__ Th,
    __nv_bfloat16* __restrict__ Tl, int K, int N)
{
    __shared__ float tile[32][33];
    int n0 = blockIdx.x * 32, k0 = blockIdx.y * 32;
    int tx = threadIdx.x, ty = threadIdx.y;
#pragma unroll
    for (int j = 0; j < 4; j++)
        tile[ty + 8 * j][tx] = W[(size_t)(k0 + ty + 8 * j) * N + n0 + tx];
    __syncthreads();
#pragma unroll
    for (int j = 0; j < 4; j++) {
        float v = tile[tx][ty + 8 * j];
        __nv_bfloat16 h = __float2bfloat16(v);
        size_t o = (size_t)(n0 + ty + 8 * j) * K + k0 + tx;
        Th[o] = h;
        Tl[o] = __float2bfloat16(v - __bfloat162float(h));
    }
}

// =========================================================================
// HMMA split-bf16 GEMM, fused 3 terms per K-chunk.
// MODE 0: C = A@B^T + bias (plain epilogue).
// MODE 1: QKV epilogue — per-head LayerNorm of q,k (+0.125 on q), plain
//         split of v, written straight to g_q*/g_k*/g_v* in [bh][p][hd].
// =========================================================================
constexpr int TILE_B2 = 128 * 80;        // 10240 bytes per tile
constexpr int BUF_B2 = 4 * TILE_B2;      // 40960 per buffer (Ah,Al,Bh,Bl)
constexpr int GEMM_SMEM = 2 * BUF_B2;    // 81920

template<int MODE>
__global__ __launch_bounds__(256, 2) void gemm_mma(
    const __nv_bfloat16* __restrict__ Ah, const __nv_bfloat16* __restrict__ Al,
    const __nv_bfloat16* __restrict__ Bh, const __nv_bfloat16* __restrict__ Bl,
    const float* __restrict__ bias, float* __restrict__ C, int M, int N, int K,
    const float* __restrict__ qs, const float* __restrict__ qb,
    const float* __restrict__ ks, const float* __restrict__ kb)
{
    extern __shared__ char sm[];
    uint32_t sbase = smem_u32(sm);
    int tid = threadIdx.x, lane = tid & 31, wid = tid >> 5;
    int bm = blockIdx.y * 128, bn = blockIdx.x * 128;
    int m0 = (wid >> 2) * 64, n0 = (wid & 3) * 32;

    const int nch = K / 32;

    auto issue_load = [&](int c, int buf) {
        const __nv_bfloat16* Ahp = Ah + (size_t)bm * K + c * 32;
        const __nv_bfloat16* Alp = Al + (size_t)bm * K + c * 32;
        const __nv_bfloat16* Bhp = Bh + (size_t)bn * K + c * 32;
        const __nv_bfloat16* Blp = Bl + (size_t)bn * K + c * 32;
        uint32_t base = sbase + buf * BUF_B2;
#pragma unroll
        for (int i = 0; i < 2; i++) {
            int u = tid + i * 256;       // 0..511
            int row = u >> 2, cc = u & 3;
            uint32_t so = row * 80 + cc * 16;
            size_t go = (size_t)row * K + cc * 8;
            CP_ASYNC16(base + so,               Ahp + go);
            CP_ASYNC16(base + TILE_B2 + so,     Alp + go);
            CP_ASYNC16(base + 2 * TILE_B2 + so, Bhp + go);
            CP_ASYNC16(base + 3 * TILE_B2 + so, Blp + go);
        }
        CP_COMMIT();
    };

    float acc[4][4][4];
#pragma unroll
    for (int mt = 0; mt < 4; mt++)
#pragma unroll
        for (int nt = 0; nt < 4; nt++)
#pragma unroll
            for (int j = 0; j < 4; j++) acc[mt][nt][j] = 0.f;

    issue_load(0, 0);
    for (int c = 0; c < nch; c++) {
        CP_WAIT0();
        __syncthreads();
        if (c + 1 < nch) issue_load(c + 1, (c + 1) & 1);

        uint32_t as  = sbase + (c & 1) * BUF_B2;
        uint32_t als = as + TILE_B2;
        uint32_t bs  = as + 2 * TILE_B2;
        uint32_t bls = as + 3 * TILE_B2;
#pragma unroll
        for (int ks_ = 0; ks_ < 2; ks_++) {
            int k0 = ks_ * 16;
            uint32_t arow = (m0 + (lane & 15)) * 80 + (k0 + (lane >> 4) * 8) * 2;
            int nn = n0 + (lane >> 4) * 8 + (lane & 7);
            int kk = k0 + ((lane >> 3) & 1) * 8;

            uint32_t aH[4][4];
#pragma unroll
            for (int mt = 0; mt < 4; mt++)
                ldsm_x4(aH[mt][0], aH[mt][1], aH[mt][2], aH[mt][3],
                        as + arow + mt * 16 * 80);
            uint32_t bH[4][2];
#pragma unroll
            for (int p = 0; p < 2; p++) {
                uint32_t r0, r1, r2, r3;
                ldsm_x4(r0, r1, r2, r3, bs + (nn + p * 16) * 80 + kk * 2);
                bH[2 * p][0] = r0; bH[2 * p][1] = r1;
                bH[2 * p + 1][0] = r2; bH[2 * p + 1][1] = r3;
            }
#pragma unroll
            for (int mt = 0; mt < 4; mt++)
#pragma unroll
                for (int nt = 0; nt < 4; nt++)
                    mma16816(acc[mt][nt], aH[mt], bH[nt]);

            uint32_t aL[4][4];
#pragma unroll
            for (int mt = 0; mt < 4; mt++)
                ldsm_x4(aL[mt][0], aL[mt][1], aL[mt][2], aL[mt][3],
                        als + arow + mt * 16 * 80);
#pragma unroll
            for (int mt = 0; mt < 4; mt++)
#pragma unroll
                for (int nt = 0; nt < 4; nt++)
                    mma16816(acc[mt][nt], aL[mt], bH[nt]);

            uint32_t bL[4][2];
#pragma unroll
            for (int p = 0; p < 2; p++) {
                uint32_t r0, r1, r2, r3;
                ldsm_x4(r0, r1, r2, r3, bls + (nn + p * 16) * 80 + kk * 2);
                bL[2 * p][0] = r0; bL[2 * p][1] = r1;
                bL[2 * p + 1][0] = r2; bL[2 * p + 1][1] = r3;
            }
#pragma unroll
            for (int mt = 0; mt < 4; mt++)
#pragma unroll
                for (int nt = 0; nt < 4; nt++)
                    mma16816(acc[mt][nt], aH[mt], bL[nt]);
        }
    }

    int g = lane >> 2, q4 = lane & 3;

    if (MODE == 0) {
        int t2 = q4 * 2;
#pragma unroll
        for (int mt = 0; mt < 4; mt++) {
            int row = bm + m0 + mt * 16 + g;
#pragma unroll
            for (int nt = 0; nt < 4; nt++) {
                int col = bn + n0 + nt * 8 + t2;
                float bx = 0.f, by = 0.f;
                if (bias) { bx = bias[col]; by = bias[col + 1]; }
                float2 lo = make_float2(acc[mt][nt][0] + bx, acc[mt][nt][1] + by);
                float2 hi = make_float2(acc[mt][nt][2] + bx, acc[mt][nt][3] + by);
                *(float2*)&C[(size_t)row * N + col] = lo;
                *(float2*)&C[(size_t)(row + 8) * N + col] = hi;
            }
        }
    } else {
        // ---------- fused QKV epilogue ----------
        __syncthreads();                 // mainloop smem reads fully done
        float* red = (float*)sm;         // [128 rows][8 warps], +1024 for sumsq
        int sec = bn / D;                // 0=q, 1=k, 2=v
        int head = ((bn - sec * D) >> 6) + ((wid & 3) >> 1);

        float mean_[4][2], inv_[4][2];
        if (sec < 2) {
#pragma unroll
            for (int mt = 0; mt < 4; mt++) {
                float s0 = 0.f, s1 = 0.f, sq0 = 0.f, sq1 = 0.f;
#pragma unroll
                for (int nt = 0; nt < 4; nt++) {
                    float a0 = acc[mt][nt][0], a1 = acc[mt][nt][1];
                    float a2 = acc[mt][nt][2], a3 = acc[mt][nt][3];
                    s0 += a0 + a1;  sq0 += a0 * a0 + a1 * a1;
                    s1 += a2 + a3;  sq1 += a2 * a2 + a3 * a3;
                }
                s0 += __shfl_xor_sync(0xffffffffu, s0, 1);
                s0 += __shfl_xor_sync(0xffffffffu, s0, 2);
                s1 += __shfl_xor_sync(0xffffffffu, s1, 1);
                s1 += __shfl_xor_sync(0xffffffffu, s1, 2);
                sq0 += __shfl_xor_sync(0xffffffffu, sq0, 1);
                sq0 += __shfl_xor_sync(0xffffffffu, sq0, 2);
                sq1 += __shfl_xor_sync(0xffffffffu, sq1, 1);
                sq1 += __shfl_xor_sync(0xffffffffu, sq1, 2);
                if (q4 == 0) {
                    int r0 = m0 + mt * 16 + g;
                    red[r0 * 8 + wid] = s0;
                    red[1024 + r0 * 8 + wid] = sq0;
                    red[(r0 + 8) * 8 + wid] = s1;
                    red[1024 + (r0 + 8) * 8 + wid] = sq1;
                }
            }
            __syncthreads();
#pragma unroll
            for (int mt = 0; mt < 4; mt++)
#pragma unroll
                for (int rp = 0; rp < 2; rp++) {
                    int r = m0 + mt * 16 + g + rp * 8;
                    float S = red[r * 8 + wid] + red[r * 8 + (wid ^ 1)];
                    float Q = red[1024 + r * 8 + wid] + red[1024 + r * 8 + (wid ^ 1)];
                    float mn = S * (1.0f / 64.0f);
                    mean_[mt][rp] = mn;
                    inv_[mt][rp] = rsqrtf(Q * (1.0f / 64.0f) - mn * mn + EPS);
                }
        }

        const float* sc = (sec == 0) ? qs : ks;
        const float* bi = (sec == 0) ? qb : kb;
        float mul = (sec == 0) ? 0.125f : 1.0f;
        __nv_bfloat16 *dh, *dl;
        if (sec == 0)      { dh = g_qh; dl = g_ql; }
        else if (sec == 1) { dh = g_kh; dl = g_kl; }
        else               { dh = g_vh; dl = g_vl; }

#pragma unroll
        for (int mt = 0; mt < 4; mt++)
#pragma unroll
            for (int rp = 0; rp < 2; rp++) {
                int r = m0 + mt * 16 + g + rp * 8;
                int tok = bm + r;
                int b_ = tok >> 11, p_ = tok & 2047;
                size_t base = ((size_t)(b_ * H + head) * P + p_) * HD;
#pragma unroll
                for (int nt = 0; nt < 4; nt++) {
                    int cih = (n0 & 63) + nt * 8 + q4 * 2;
                    float v0 = acc[mt][nt][rp * 2];
                    float v1 = acc[mt][nt][rp * 2 + 1];
                    float y0, y1;
                    if (sec < 2) {
                        float mn = mean_[mt][rp], iv = inv_[mt][rp];
                        y0 = ((v0 - mn) * iv * sc[cih]     + bi[cih])     * mul;
                        y1 = ((v1 - mn) * iv * sc[cih + 1] + bi[cih + 1]) * mul;
                    } else { y0 = v0; y1 = v1; }
                    __nv_bfloat162 Hh = __float22bfloat162_rn(make_float2(y0, y1));
                    __nv_bfloat162 Ll = __float22bfloat162_rn(
                        make_float2(y0 - __low2float(Hh), y1 - __high2float(Hh)));
                    *(__nv_bfloat162*)&dh[base + cih] = Hh;
                    *(__nv_bfloat162*)&dl[base + cih] = Ll;
                }
            }
    }
}

// =========================================================================
// Flash attention on HMMA, split-bf16, Q-in-regs, double-buffered KV,
// KV-SPLIT: grid (B*H, P/128, KVS); split s handles keys
// [s*P/KVS, (s+1)*P/KVS).  Writes unnormalized partial O + (m,l).
// =========================================================================
constexpr int KVBUF = 36864;                 // kh,kl,vh,vl each 9216 B
constexpr int ATT_SMEM = 2 * KVBUF;          // 73728

__global__ __launch_bounds__(256, 2) void attn_mma()
{
    extern __shared__ char sm[];
    uint32_t sb = smem_u32(sm);

    int bh = blockIdx.x, q0 = blockIdx.y * 128, s = blockIdx.z;
    int b = bh / H, h = bh - b * H;
    int tid = threadIdx.x, lane = tid & 31, w = tid >> 5;
    const int m0 = w * 16;
    const int NKB = P / 64 / KVS;            // key blocks per split
    const int kb0 = s * NKB;

    const uint32_t sqh = sb, sql = sb + 18432;
    size_t qbase = ((size_t)bh * P + q0) * HD;
#pragma unroll
    for (int i = 0; i < 4; i++) {
        int u = tid + i * 256;
        int row = u >> 3, c = u & 7;
        CP_ASYNC16(sqh + row * 144 + c * 16, g_qh + qbase + (size_t)row * HD + c * 8);
        CP_ASYNC16(sql + row * 144 + c * 16, g_ql + qbase + (size_t)row * HD + c * 8);
    }

    auto kv_issue = [&](int kb, uint32_t kbuf) {
        size_t kbase = ((size_t)bh * P + (kb0 + kb) * 64) * HD;
#pragma unroll
        for (int i = 0; i < 2; i++) {
            int u = tid + i * 256;
            int row = u >> 3, c = u & 7;
            uint32_t so = row * 144 + c * 16;
            size_t go = (size_t)row * HD + c * 8;
            CP_ASYNC16(kbuf + so,         g_kh + kbase + go);
            CP_ASYNC16(kbuf + 9216 + so,  g_kl + kbase + go);
            CP_ASYNC16(kbuf + 18432 + so, g_vh + kbase + go);
            CP_ASYNC16(kbuf + 27648 + so, g_vl + kbase + go);
        }
        CP_COMMIT();
    };

    kv_issue(0, sb + KVBUF);
    CP_WAIT0();
    __syncthreads();

    uint32_t qaH[4][4], qaL[4][4];
#pragma unroll
    for (int ks = 0; ks < 4; ks++) {
        uint32_t qoff = (m0 + (lane & 15)) * 144 + (ks * 16 + (lane >> 4) * 8) * 2;
        ldsm_x4(qaH[ks][0], qaH[ks][1], qaH[ks][2], qaH[ks][3], sqh + qoff);
        ldsm_x4(qaL[ks][0], qaL[ks][1], qaL[ks][2], qaL[ks][3], sql + qoff);
    }
    __syncthreads();
    kv_issue(1, sb);

    float m0r = -1e30f, m1r = -1e30f, l0r = 0.f, l1r = 0.f;
    float O[8][4];
#pragma unroll
    for (int nt = 0; nt < 8; nt++)
#pragma unroll
        for (int j = 0; j < 4; j++) O[nt][j] = 0.f;

    for (int kb = 0; kb < NKB; kb++) {
        if (kb > 0) {
            CP_WAIT0();
            __syncthreads();
            if (kb + 1 < NKB)
                kv_issue(kb + 1, ((kb + 1) & 1) ? sb : sb + KVBUF);
        }
        uint32_t kbuf = (kb & 1) ? sb : sb + KVBUF;
        uint32_t skh = kbuf, skl = kbuf + 9216;
        uint32_t svh = kbuf + 18432, svl = kbuf + 27648;

        float sa[8][4];
#pragma unroll
        for (int nt = 0; nt < 8; nt++)
#pragma unroll
            for (int j = 0; j < 4; j++) sa[nt][j] = 0.f;

#pragma unroll
        for (int ks = 0; ks < 4; ks++) {
            int k0 = ks * 16;
#pragma unroll
            for (int j = 0; j < 4; j++) {
                int n0 = j * 16;
                uint32_t koff = (n0 + (lane >> 4) * 8 + (lane & 7)) * 144
                              + (k0 + ((lane >> 3) & 1) * 8) * 2;
                uint32_t bH[4], bL[4];
                ldsm_x4(bH[0], bH[1], bH[2], bH[3], skh + koff);
                ldsm_x4(bL[0], bL[1], bL[2], bL[3], skl + koff);
                mma16816(sa[2 * j],     qaH[ks], &bH[0]);
                mma16816(sa[2 * j + 1], qaH[ks], &bH[2]);
                mma16816(sa[2 * j],     qaL[ks], &bH[0]);
                mma16816(sa[2 * j + 1], qaL[ks], &bH[2]);
                mma16816(sa[2 * j],     qaH[ks], &bL[0]);
                mma16816(sa[2 * j + 1], qaH[ks], &bL[2]);
            }
        }

        float mx0 = -1e30f, mx1 = -1e30f;
#pragma unroll
        for (int nt = 0; nt < 8; nt++) {
            mx0 = fmaxf(mx0, fmaxf(sa[nt][0], sa[nt][1]));
            mx1 = fmaxf(mx1, fmaxf(sa[nt][2], sa[nt][3]));
        }
        mx0 = fmaxf(mx0, __shfl_xor_sync(0xffffffffu, mx0, 1));
        mx0 = fmaxf(mx0, __shfl_xor_sync(0xffffffffu, mx0, 2));
        mx1 = fmaxf(mx1, __shfl_xor_sync(0xffffffffu, mx1, 1));
        mx1 = fmaxf(mx1, __shfl_xor_sync(0xffffffffu, mx1, 2));
        float mn0 = fmaxf(m0r, mx0), mn1 = fmaxf(m1r, mx1);
        float c0 = __expf(m0r - mn0), c1 = __expf(m1r - mn1);
        m0r = mn0; m1r = mn1;

        float s0 = 0.f, s1 = 0.f;
        uint32_t ph0[8], ph1[8], pl0[8], pl1[8];
#pragma unroll
        for (int nt = 0; nt < 8; nt++) {
            float2 e0 = make_float2(__expf(sa[nt][0] - mn0), __expf(sa[nt][1] - mn0));
            float2 e1 = make_float2(__expf(sa[nt][2] - mn1), __expf(sa[nt][3] - mn1));
            s0 += e0.x + e0.y;
            s1 += e1.x + e1.y;
            __nv_bfloat162 H0 = __float22bfloat162_rn(e0);
            __nv_bfloat162 H1 = __float22bfloat162_rn(e1);
            ph0[nt] = *(uint32_t*)&H0;
            ph1[nt] = *(uint32_t*)&H1;
            __nv_bfloat162 L0 = __float22bfloat162_rn(
                make_float2(e0.x - __low2float(H0), e0.y - __high2float(H0)));
            __nv_bfloat162 L1 = __float22bfloat162_rn(
                make_float2(e1.x - __low2float(H1), e1.y - __high2float(H1)));
            pl0[nt] = *(uint32_t*)&L0;
            pl1[nt] = *(uint32_t*)&L1;
        }
        s0 += __shfl_xor_sync(0xffffffffu, s0, 1);
        s0 += __shfl_xor_sync(0xffffffffu, s0, 2);
        s1 += __shfl_xor_sync(0xffffffffu, s1, 1);
        s1 += __shfl_xor_sync(0xffffffffu, s1, 2);
        l0r = l0r * c0 + s0;
        l1r = l1r * c1 + s1;
#pragma unroll
        for (int nt = 0; nt < 8; nt++) {
            O[nt][0] *= c0; O[nt][1] *= c0;
            O[nt][2] *= c1; O[nt][3] *= c1;
        }

#pragma unroll
        for (int ks = 0; ks < 4; ks++) {
            int k0 = ks * 16;
            uint32_t aPh[4] = {ph0[2 * ks], ph1[2 * ks], ph0[2 * ks + 1], ph1[2 * ks + 1]};
            uint32_t aPl[4] = {pl0[2 * ks], pl1[2 * ks], pl0[2 * ks + 1], pl1[2 * ks + 1]};
#pragma unroll
            for (int jn = 0; jn < 4; jn++) {
                int n0 = jn * 16;
                uint32_t voff = (k0 + ((lane >> 3) & 1) * 8 + (lane & 7)) * 144
                              + (n0 + (lane >> 4) * 8) * 2;
                uint32_t vH[4], vL[4];
                ldsm_x4_t(vH[0], vH[1], vH[2], vH[3], svh + voff);
                ldsm_x4_t(vL[0], vL[1], vL[2], vL[3], svl + voff);
                mma16816(O[2 * jn],     aPh, &vH[0]);
                mma16816(O[2 * jn + 1], aPh, &vH[2]);
                mma16816(O[2 * jn],     aPl, &vH[0]);
                mma16816(O[2 * jn + 1], aPl, &vH[2]);
                mma16816(O[2 * jn],     aPh, &vL[0]);
                mma16816(O[2 * jn + 1], aPh, &vL[2]);
            }
        }
    }

    // ---- epilogue: unnormalized partial O + (m, l) per row ----
    int r0 = q0 + m0 + (lane >> 2), r1 = r0 + 8;
    if ((lane & 3) == 0) {
        size_t mlb = ((size_t)s * B * H + bh) * P;
        g_ml[mlb + r0] = make_float2(m0r, l0r);
        g_ml[mlb + r1] = make_float2(m1r, l1r);
    }
    float* Op = g_attp + (size_t)s * TOK * D;
#pragma unroll
    for (int nt = 0; nt < 8; nt++) {
        int col = h * HD + nt * 8 + (lane & 3) * 2;
        *(float2*)&Op[(size_t)(b * P + r0) * D + col] = make_float2(O[nt][0], O[nt][1]);
        *(float2*)&Op[(size_t)(b * P + r1) * D + col] = make_float2(O[nt][2], O[nt][3]);
    }
}

// =========================================================================
// Combine KV-split partials + final LayerNorm over D=768, emits split bf16.
// =========================================================================
__global__ __launch_bounds__(256) void ln_final(
    const float* __restrict__ sc, const float* __restrict__ bi)
{
    __shared__ float red[8];
    int t = blockIdx.x;
    int tid = threadIdx.x;
    int b_ = t >> 11, p_ = t & 2047;
    const float* x0p = g_attp + (size_t)t * D;
    const float* x1p = g_attp + (size_t)TOK * D + (size_t)t * D;

    float v[3];
#pragma unroll
    for (int j = 0; j < 3; j++) {
        int idx = tid + j * 256;
        int head = idx >> 6;
        size_t mlb = (size_t)(b_ * H + head) * P + p_;
        float2 ml0 = g_ml[mlb];
        float2 ml1 = g_ml[(size_t)B * H * P + mlb];
        float m = fmaxf(ml0.x, ml1.x);
        float e0 = __expf(ml0.x - m), e1 = __expf(ml1.x - m);
        float den = e0 * ml0.y + e1 * ml1.y;
        v[j] = (e0 * x0p[idx] + e1 * x1p[idx]) / den;
    }

    float s = v[0] + v[1] + v[2];
#pragma unroll
    for (int o = 16; o; o >>= 1) s += __shfl_xor_sync(0xffffffffu, s, o);
    if ((tid & 31) == 0) red[tid >> 5] = s;
    __syncthreads();
    float tot = 0.f;
#pragma unroll
    for (int w = 0; w < 8; w++) tot += red[w];
    float mean = tot * (1.0f / 768.0f);

    float d0 = v[0] - mean, d1 = v[1] - mean, d2 = v[2] - mean;
    float vv = d0 * d0 + d1 * d1 + d2 * d2;
#pragma unroll
    for (int o = 16; o; o >>= 1) vv += __shfl_xor_sync(0xffffffffu, vv, o);
    __syncthreads();
    if ((tid & 31) == 0) red[tid >> 5] = vv;
    __syncthreads();
    float vt = 0.f;
#pragma unroll
    for (int w = 0; w < 8; w++) vt += red[w];
    float inv = rsqrtf(vt * (1.0f / 768.0f) + EPS);

#pragma unroll
    for (int j = 0; j < 3; j++) {
        int idx = tid + j * 256;
        float dj = (j == 0 ? d0 : (j == 1 ? d1 : d2));
        float y = dj * inv * sc[idx] + bi[idx];
        __nv_bfloat16 hh = __float2bfloat16(y);
        size_t o = (size_t)t * D + idx;
        g_a2h[o] = hh;
        g_a2l[o] = __float2bfloat16(y - __bfloat162float(hh));
    }
}

// =========================================================================
extern "C" void kernel_launch(void* const* d_in, const int* in_sizes, int n_in,
                              void* d_out, int out_size)
{
    const float* x       = (const float*)d_in[0];
    const float* Wqkv    = (const float*)d_in[1];
    const float* q_scale = (const float*)d_in[2];
    const float* q_bias  = (const float*)d_in[3];
    const float* k_scale = (const float*)d_in[4];
    const float* k_bias  = (const float*)d_in[5];
    const float* o_scale = (const float*)d_in[6];
    const float* o_bias  = (const float*)d_in[7];
    const float* Wout    = (const float*)d_in[8];
    const float* bout    = (const float*)d_in[9];
    float* out = (float*)d_out;

    __nv_bfloat16 *p_xh, *p_xl, *p_wqh, *p_wql, *p_woh, *p_wol, *p_a2h, *p_a2l;
    cudaGetSymbolAddress((void**)&p_xh, g_xh);
    cudaGetSymbolAddress((void**)&p_xl, g_xl);
    cudaGetSymbolAddress((void**)&p_wqh, g_wqh);
    cudaGetSymbolAddress((void**)&p_wql, g_wql);
    cudaGetSymbolAddress((void**)&p_woh, g_woh);
    cudaGetSymbolAddress((void**)&p_wol, g_wol);
    cudaGetSymbolAddress((void**)&p_a2h, g_a2h);
    cudaGetSymbolAddress((void**)&p_a2l, g_a2l);

    cudaFuncSetAttribute(gemm_mma<0>, cudaFuncAttributeMaxDynamicSharedMemorySize, GEMM_SMEM);
    cudaFuncSetAttribute(gemm_mma<1>, cudaFuncAttributeMaxDynamicSharedMemorySize, GEMM_SMEM);
    cudaFuncSetAttribute(attn_mma, cudaFuncAttributeMaxDynamicSharedMemorySize, ATT_SMEM);

    // 0) split inputs/weights into bf16 hi/lo
    conv_split<<<(TOK * D / 4 + 255) / 256, 256>>>(x, p_xh, p_xl, TOK * D / 4);
    conv_wT<<<dim3(QKVN / 32, D / 32), dim3(32, 8)>>>(Wqkv, p_wqh, p_wql, D, QKVN);
    conv_wT<<<dim3(D / 32, D / 32), dim3(32, 8)>>>(Wout, p_woh, p_wol, D, D);

    // 1) QKV projection with fused per-head LN + split epilogue
    gemm_mma<1><<<dim3(QKVN / 128, TOK / 128), 256, GEMM_SMEM>>>(
        p_xh, p_xl, p_wqh, p_wql, nullptr, nullptr, TOK, QKVN, D,
        q_scale, q_bias, k_scale, k_bias);

    // 2) flash attention (HMMA, KV-split x2)
    attn_mma<<<dim3(B * H, P / 128, KVS), 256, ATT_SMEM>>>();

    // 3) combine + final LN over D (emits split bf16)
    ln_final<<<TOK, 256>>>(o_scale, o_bias);

    // 4) output projection (HMMA, fused 3-term) with bias
    gemm_mma<0><<<dim3(D / 128, TOK / 128), 256, GEMM_SMEM>>>(
        p_a2h, p_a2l, p_woh, p_wol, bout, out, TOK, D, D,
        nullptr, nullptr, nullptr, nullptr);
}

// round 15
// speedup vs baseline: 1.3901x; 1.3901x over previous
#include <cuda_runtime.h>
#include <cuda_fp16.h>
#include <cstdint>
#include <math.h>

#define EPS 1e-6f
constexpr int B = 2, P = 2048, D = 768, H = 12, HD = 64;
constexpr int TOK = B * P;        // 4096
constexpr int QKVN = 3 * D;       // 2304

// ---------------- scratch (static device globals; no allocation) ----------------
__device__ float g_att[TOK * D];          // attention output, token-major

// split-fp16 operands (A-side split hi/lo, B-side single)
__device__ __half g_xh[TOK * D];
__device__ __half g_xl[TOK * D];
__device__ __half g_wqh[QKVN * D];        // W_qkv^T single fp16 [2304][768]
__device__ __half g_woh[D * D];           // W_out^T single fp16
__device__ __half g_a2h[TOK * D];         // ln_final out hi
__device__ __half g_a2l[TOK * D];         // ln_final out lo
// attention operands, [bh][p][hd]
__device__ __half g_qh[B * H * P * HD];   // q split hi
__device__ __half g_ql[B * H * P * HD];   // q split lo
__device__ __half g_kh[B * H * P * HD];   // k single
__device__ __half g_vh[B * H * P * HD];   // v single

// ======================= base-target PTX helpers =======================
__device__ __forceinline__ uint32_t smem_u32(const void* p) {
    uint32_t a;
    asm("{ .reg .u64 t; cvta.to.shared.u64 t, %1; cvt.u32.u64 %0, t; }" : "=r"(a) : "l"(p));
    return a;
}
#define CP_ASYNC16(dst, src) \
    asm volatile("cp.async.cg.shared.global [%0], [%1], 16;" :: "r"(dst), "l"(src))
#define CP_COMMIT() asm volatile("cp.async.commit_group;" ::: "memory")
#define CP_WAIT0()  asm volatile("cp.async.wait_group 0;" ::: "memory")

__device__ __forceinline__ void ldsm_x4(uint32_t& r0, uint32_t& r1, uint32_t& r2,
                                        uint32_t& r3, uint32_t addr) {
    asm volatile("ldmatrix.sync.aligned.m8n8.x4.shared.b16 {%0,%1,%2,%3}, [%4];"
                 : "=r"(r0), "=r"(r1), "=r"(r2), "=r"(r3) : "r"(addr));
}
__device__ __forceinline__ void ldsm_x4_t(uint32_t& r0, uint32_t& r1, uint32_t& r2,
                                          uint32_t& r3, uint32_t addr) {
    asm volatile("ldmatrix.sync.aligned.m8n8.x4.trans.shared.b16 {%0,%1,%2,%3}, [%4];"
                 : "=r"(r0), "=r"(r1), "=r"(r2), "=r"(r3) : "r"(addr));
}
__device__ __forceinline__ void mma16816(float* c, const uint32_t* a, const uint32_t* b) {
    asm volatile(
        "mma.sync.aligned.m16n8k16.row.col.f32.f16.f16.f32 "
        "{%0,%1,%2,%3}, {%4,%5,%6,%7}, {%8,%9}, {%0,%1,%2,%3};"
        : "+f"(c[0]), "+f"(c[1]), "+f"(c[2]), "+f"(c[3])
        : "r"(a[0]), "r"(a[1]), "r"(a[2]), "r"(a[3]), "r"(b[0]), "r"(b[1]));
}

// =========================================================================
// Split fp32 -> fp16 hi/lo, same layout.
// =========================================================================
__global__ __launch_bounds__(256) void conv_split(
    const float* __restrict__ src, __half* __restrict__ hi,
    __half* __restrict__ lo, int n4)
{
    int i = blockIdx.x * blockDim.x + threadIdx.x;
    if (i >= n4) return;
    float4 v = ((const float4*)src)[i];
    __half h0 = __float2half_rn(v.x), h1 = __float2half_rn(v.y);
    __half h2 = __float2half_rn(v.z), h3 = __float2half_rn(v.w);
    __half2* hp = (__half2*)hi;
    __half2* lp = (__half2*)lo;
    hp[2 * i] = __half2(h0, h1);
    hp[2 * i + 1] = __half2(h2, h3);
    lp[2 * i] = __half2(__float2half_rn(v.x - __half2float(h0)),
                        __float2half_rn(v.y - __half2float(h1)));
    lp[2 * i + 1] = __half2(__float2half_rn(v.z - __half2float(h2)),
                            __float2half_rn(v.w - __half2float(h3)));
}

// =========================================================================
// Transpose: W[K][N] f32 -> T[N][K] single fp16.  32x32 tiles.
// =========================================================================
__global__ __launch_bounds__(256) void conv_wT(
    const float* __restrict__ W, __half* __restrict__ Th, int K, int N)
{
    __shared__ float tile[32][33];
    int n0 = blockIdx.x * 32, k0 = blockIdx.y * 32;
    int tx = threadIdx.x, ty = threadIdx.y;
#pragma unroll
    for (int j = 0; j < 4; j++)
        tile[ty + 8 * j][tx] = W[(size_t)(k0 + ty + 8 * j) * N + n0 + tx];
    __syncthreads();
#pragma unroll
    for (int j = 0; j < 4; j++)
        Th[(size_t)(n0 + ty + 8 * j) * K + k0 + tx] =
            __float2half_rn(tile[tx][ty + 8 * j]);
}

// =========================================================================
// HMMA fp16 2-term GEMM: C = Ah@Bh^T + Al@Bh^T (+bias), fp32 accum.
// MODE 0: plain epilogue.  MODE 1: fused QKV epilogue (LN q,k; split q;
// single k,v) into attention layout.
// 128x128 CTA tile, 8 warps, KC=32, double-buffered cp.async.
// =========================================================================
constexpr int TILE_B2 = 128 * 80;        // 10240 bytes per tile
constexpr int BUF_B2 = 3 * TILE_B2;      // Ah, Al, Bh
constexpr int GEMM_SMEM = 2 * BUF_B2;    // 61440

template<int MODE>
__global__ __launch_bounds__(256, 2) void gemm_mma(
    const __half* __restrict__ Ah, const __half* __restrict__ Al,
    const __half* __restrict__ Bh,
    const float* __restrict__ bias, float* __restrict__ C, int M, int N, int K,
    const float* __restrict__ qs, const float* __restrict__ qb,
    const float* __restrict__ ks, const float* __restrict__ kb)
{
    extern __shared__ char sm[];
    uint32_t sbase = smem_u32(sm);
    int tid = threadIdx.x, lane = tid & 31, wid = tid >> 5;
    int bm = blockIdx.y * 128, bn = blockIdx.x * 128;
    int m0 = (wid >> 2) * 64, n0 = (wid & 3) * 32;

    const int nch = K / 32;

    auto issue_load = [&](int c, int buf) {
        const __half* Ahp = Ah + (size_t)bm * K + c * 32;
        const __half* Alp = Al + (size_t)bm * K + c * 32;
        const __half* Bhp = Bh + (size_t)bn * K + c * 32;
        uint32_t base = sbase + buf * BUF_B2;
#pragma unroll
        for (int i = 0; i < 2; i++) {
            int u = tid + i * 256;       // 0..511
            int row = u >> 2, cc = u & 3;
            uint32_t so = row * 80 + cc * 16;
            size_t go = (size_t)row * K + cc * 8;
            CP_ASYNC16(base + so,               Ahp + go);
            CP_ASYNC16(base + TILE_B2 + so,     Alp + go);
            CP_ASYNC16(base + 2 * TILE_B2 + so, Bhp + go);
        }
        CP_COMMIT();
    };

    float acc[4][4][4];
#pragma unroll
    for (int mt = 0; mt < 4; mt++)
#pragma unroll
        for (int nt = 0; nt < 4; nt++)
#pragma unroll
            for (int j = 0; j < 4; j++) acc[mt][nt][j] = 0.f;

    issue_load(0, 0);
    for (int c = 0; c < nch; c++) {
        CP_WAIT0();
        __syncthreads();
        if (c + 1 < nch) issue_load(c + 1, (c + 1) & 1);

        uint32_t as  = sbase + (c & 1) * BUF_B2;
        uint32_t als = as + TILE_B2;
        uint32_t bs  = as + 2 * TILE_B2;
#pragma unroll
        for (int ks_ = 0; ks_ < 2; ks_++) {
            int k0 = ks_ * 16;
            uint32_t arow = (m0 + (lane & 15)) * 80 + (k0 + (lane >> 4) * 8) * 2;
            int nn = n0 + (lane >> 4) * 8 + (lane & 7);
            int kk = k0 + ((lane >> 3) & 1) * 8;

            uint32_t aH[4][4];
#pragma unroll
            for (int mt = 0; mt < 4; mt++)
                ldsm_x4(aH[mt][0], aH[mt][1], aH[mt][2], aH[mt][3],
                        as + arow + mt * 16 * 80);
            uint32_t bH[4][2];
#pragma unroll
            for (int p = 0; p < 2; p++) {
                uint32_t r0, r1, r2, r3;
                ldsm_x4(r0, r1, r2, r3, bs + (nn + p * 16) * 80 + kk * 2);
                bH[2 * p][0] = r0; bH[2 * p][1] = r1;
                bH[2 * p + 1][0] = r2; bH[2 * p + 1][1] = r3;
            }
#pragma unroll
            for (int mt = 0; mt < 4; mt++)
#pragma unroll
                for (int nt = 0; nt < 4; nt++)
                    mma16816(acc[mt][nt], aH[mt], bH[nt]);

            uint32_t aL[4][4];
#pragma unroll
            for (int mt = 0; mt < 4; mt++)
                ldsm_x4(aL[mt][0], aL[mt][1], aL[mt][2], aL[mt][3],
                        als + arow + mt * 16 * 80);
#pragma unroll
            for (int mt = 0; mt < 4; mt++)
#pragma unroll
                for (int nt = 0; nt < 4; nt++)
                    mma16816(acc[mt][nt], aL[mt], bH[nt]);
        }
    }

    int g = lane >> 2, q4 = lane & 3;

    if (MODE == 0) {
        int t2 = q4 * 2;
#pragma unroll
        for (int mt = 0; mt < 4; mt++) {
            int row = bm + m0 + mt * 16 + g;
#pragma unroll
            for (int nt = 0; nt < 4; nt++) {
                int col = bn + n0 + nt * 8 + t2;
                float bx = 0.f, by = 0.f;
                if (bias) { bx = bias[col]; by = bias[col + 1]; }
                float2 lo = make_float2(acc[mt][nt][0] + bx, acc[mt][nt][1] + by);
                float2 hi = make_float2(acc[mt][nt][2] + bx, acc[mt][nt][3] + by);
                *(float2*)&C[(size_t)row * N + col] = lo;
                *(float2*)&C[(size_t)(row + 8) * N + col] = hi;
            }
        }
    } else {
        // ---------- fused QKV epilogue ----------
        __syncthreads();                 // mainloop smem reads fully done
        float* red = (float*)sm;         // [128 rows][8 warps], +1024 for sumsq
        int sec = bn / D;                // 0=q, 1=k, 2=v
        int head = ((bn - sec * D) >> 6) + ((wid & 3) >> 1);

        float mean_[4][2], inv_[4][2];
        if (sec < 2) {
#pragma unroll
            for (int mt = 0; mt < 4; mt++) {
                float s0 = 0.f, s1 = 0.f, sq0 = 0.f, sq1 = 0.f;
#pragma unroll
                for (int nt = 0; nt < 4; nt++) {
                    float a0 = acc[mt][nt][0], a1 = acc[mt][nt][1];
                    float a2 = acc[mt][nt][2], a3 = acc[mt][nt][3];
                    s0 += a0 + a1;  sq0 += a0 * a0 + a1 * a1;
                    s1 += a2 + a3;  sq1 += a2 * a2 + a3 * a3;
                }
                s0 += __shfl_xor_sync(0xffffffffu, s0, 1);
                s0 += __shfl_xor_sync(0xffffffffu, s0, 2);
                s1 += __shfl_xor_sync(0xffffffffu, s1, 1);
                s1 += __shfl_xor_sync(0xffffffffu, s1, 2);
                sq0 += __shfl_xor_sync(0xffffffffu, sq0, 1);
                sq0 += __shfl_xor_sync(0xffffffffu, sq0, 2);
                sq1 += __shfl_xor_sync(0xffffffffu, sq1, 1);
                sq1 += __shfl_xor_sync(0xffffffffu, sq1, 2);
                if (q4 == 0) {
                    int r0 = m0 + mt * 16 + g;
                    red[r0 * 8 + wid] = s0;
                    red[1024 + r0 * 8 + wid] = sq0;
                    red[(r0 + 8) * 8 + wid] = s1;
                    red[1024 + (r0 + 8) * 8 + wid] = sq1;
                }
            }
            __syncthreads();
#pragma unroll
            for (int mt = 0; mt < 4; mt++)
#pragma unroll
                for (int rp = 0; rp < 2; rp++) {
                    int r = m0 + mt * 16 + g + rp * 8;
                    float S = red[r * 8 + wid] + red[r * 8 + (wid ^ 1)];
                    float Q = red[1024 + r * 8 + wid] + red[1024 + r * 8 + (wid ^ 1)];
                    float mn = S * (1.0f / 64.0f);
                    mean_[mt][rp] = mn;
                    inv_[mt][rp] = rsqrtf(Q * (1.0f / 64.0f) - mn * mn + EPS);
                }
        }

        const float* sc = (sec == 0) ? qs : ks;
        const float* bi = (sec == 0) ? qb : kb;
        float mul = (sec == 0) ? 0.125f : 1.0f;

#pragma unroll
        for (int mt = 0; mt < 4; mt++)
#pragma unroll
            for (int rp = 0; rp < 2; rp++) {
                int r = m0 + mt * 16 + g + rp * 8;
                int tok = bm + r;
                int b_ = tok >> 11, p_ = tok & 2047;
                size_t base = ((size_t)(b_ * H + head) * P + p_) * HD;
#pragma unroll
                for (int nt = 0; nt < 4; nt++) {
                    int cih = (n0 & 63) + nt * 8 + q4 * 2;
                    float v0 = acc[mt][nt][rp * 2];
                    float v1 = acc[mt][nt][rp * 2 + 1];
                    if (sec == 2) {
                        *(__half2*)&g_vh[base + cih] =
                            __float22half2_rn(make_float2(v0, v1));
                    } else {
                        float mn = mean_[mt][rp], iv = inv_[mt][rp];
                        float y0 = ((v0 - mn) * iv * sc[cih]     + bi[cih])     * mul;
                        float y1 = ((v1 - mn) * iv * sc[cih + 1] + bi[cih + 1]) * mul;
                        if (sec == 1) {
                            *(__half2*)&g_kh[base + cih] =
                                __float22half2_rn(make_float2(y0, y1));
                        } else {
                            __half2 Hh = __float22half2_rn(make_float2(y0, y1));
                            __half2 Ll = __float22half2_rn(
                                make_float2(y0 - __low2float(Hh),
                                            y1 - __high2float(Hh)));
                            *(__half2*)&g_qh[base + cih] = Hh;
                            *(__half2*)&g_ql[base + cih] = Ll;
                        }
                    }
                }
            }
    }
}

// =========================================================================
// Flash attention, fp16 2-term: S = Qh K^T + Ql K^T;  O += Ph V + Pl V.
// Q fragments register-resident; KV double buffer overlaying dead Q smem.
// grid (B*H, P/128), 256 threads = 8 warps; warp w owns q rows w*16..+15.
// =========================================================================
constexpr int KVBUF = 18432;                 // kh, vh each 9216 B
constexpr int ATT_SMEM = 36864 + KVBUF;      // Q(hi+lo) staging + buf0 = 55296

__global__ __launch_bounds__(256, 2) void attn_mma()
{
    extern __shared__ char sm[];
    uint32_t sb = smem_u32(sm);

    int bh = blockIdx.x, q0 = blockIdx.y * 128;
    int b = bh / H, h = bh - b * H;
    int tid = threadIdx.x, lane = tid & 31, w = tid >> 5;
    const int m0 = w * 16;
    const int NKB = P / 64;

    // Q staged transiently at [0, 36864); buf1 will overlay it later.
    const uint32_t sqh = sb, sql = sb + 18432;
    size_t qbase = ((size_t)bh * P + q0) * HD;
#pragma unroll
    for (int i = 0; i < 4; i++) {
        int u = tid + i * 256;
        int row = u >> 3, c = u & 7;
        CP_ASYNC16(sqh + row * 144 + c * 16, g_qh + qbase + (size_t)row * HD + c * 8);
        CP_ASYNC16(sql + row * 144 + c * 16, g_ql + qbase + (size_t)row * HD + c * 8);
    }

    auto kv_issue = [&](int kb, uint32_t kbuf) {
        size_t kbase = ((size_t)bh * P + kb * 64) * HD;
#pragma unroll
        for (int i = 0; i < 2; i++) {
            int u = tid + i * 256;
            int row = u >> 3, c = u & 7;
            uint32_t so = row * 144 + c * 16;
            size_t go = (size_t)row * HD + c * 8;
            CP_ASYNC16(kbuf + so,        g_kh + kbase + go);
            CP_ASYNC16(kbuf + 9216 + so, g_vh + kbase + go);
        }
        CP_COMMIT();
    };

    kv_issue(0, sb + 36864);    // buf0 beyond Q region
    CP_WAIT0();
    __syncthreads();

    uint32_t qaH[4][4], qaL[4][4];
#pragma unroll
    for (int ks = 0; ks < 4; ks++) {
        uint32_t qoff = (m0 + (lane & 15)) * 144 + (ks * 16 + (lane >> 4) * 8) * 2;
        ldsm_x4(qaH[ks][0], qaH[ks][1], qaH[ks][2], qaH[ks][3], sqh + qoff);
        ldsm_x4(qaL[ks][0], qaL[ks][1], qaL[ks][2], qaL[ks][3], sql + qoff);
    }
    __syncthreads();   // all warps done reading Q smem before buf1 overlays it
    kv_issue(1, sb);   // buf1 = start of old Q region

    float m0r = -1e30f, m1r = -1e30f, l0r = 0.f, l1r = 0.f;
    float O[8][4];
#pragma unroll
    for (int nt = 0; nt < 8; nt++)
#pragma unroll
        for (int j = 0; j < 4; j++) O[nt][j] = 0.f;

    for (int kb = 0; kb < NKB; kb++) {
        if (kb > 0) {
            CP_WAIT0();
            __syncthreads();
            if (kb + 1 < NKB)
                kv_issue(kb + 1, ((kb + 1) & 1) ? sb : sb + 36864);
        }
        uint32_t kbuf = (kb & 1) ? sb : sb + 36864;
        uint32_t skh = kbuf, svh = kbuf + 9216;

        // ---- S = Q K^T (2-term, Q from registers) ----
        float sa[8][4];
#pragma unroll
        for (int nt = 0; nt < 8; nt++)
#pragma unroll
            for (int j = 0; j < 4; j++) sa[nt][j] = 0.f;

#pragma unroll
        for (int ks = 0; ks < 4; ks++) {
            int k0 = ks * 16;
#pragma unroll
            for (int j = 0; j < 4; j++) {
                int n0 = j * 16;
                uint32_t koff = (n0 + (lane >> 4) * 8 + (lane & 7)) * 144
                              + (k0 + ((lane >> 3) & 1) * 8) * 2;
                uint32_t bH[4];
                ldsm_x4(bH[0], bH[1], bH[2], bH[3], skh + koff);
                mma16816(sa[2 * j],     qaH[ks], &bH[0]);
                mma16816(sa[2 * j + 1], qaH[ks], &bH[2]);
                mma16816(sa[2 * j],     qaL[ks], &bH[0]);
                mma16816(sa[2 * j + 1], qaL[ks], &bH[2]);
            }
        }

        // ---- online softmax ----
        float mx0 = -1e30f, mx1 = -1e30f;
#pragma unroll
        for (int nt = 0; nt < 8; nt++) {
            mx0 = fmaxf(mx0, fmaxf(sa[nt][0], sa[nt][1]));
            mx1 = fmaxf(mx1, fmaxf(sa[nt][2], sa[nt][3]));
        }
        mx0 = fmaxf(mx0, __shfl_xor_sync(0xffffffffu, mx0, 1));
        mx0 = fmaxf(mx0, __shfl_xor_sync(0xffffffffu, mx0, 2));
        mx1 = fmaxf(mx1, __shfl_xor_sync(0xffffffffu, mx1, 1));
        mx1 = fmaxf(mx1, __shfl_xor_sync(0xffffffffu, mx1, 2));
        float mn0 = fmaxf(m0r, mx0), mn1 = fmaxf(m1r, mx1);
        float c0 = __expf(m0r - mn0), c1 = __expf(m1r - mn1);
        m0r = mn0; m1r = mn1;

        float s0 = 0.f, s1 = 0.f;
        uint32_t ph0[8], ph1[8], pl0[8], pl1[8];
#pragma unroll
        for (int nt = 0; nt < 8; nt++) {
            float2 e0 = make_float2(__expf(sa[nt][0] - mn0), __expf(sa[nt][1] - mn0));
            float2 e1 = make_float2(__expf(sa[nt][2] - mn1), __expf(sa[nt][3] - mn1));
            s0 += e0.x + e0.y;
            s1 += e1.x + e1.y;
            __half2 H0 = __float22half2_rn(e0);
            __half2 H1 = __float22half2_rn(e1);
            ph0[nt] = *(uint32_t*)&H0;
            ph1[nt] = *(uint32_t*)&H1;
            __half2 L0 = __float22half2_rn(
                make_float2(e0.x - __low2float(H0), e0.y - __high2float(H0)));
            __half2 L1 = __float22half2_rn(
                make_float2(e1.x - __low2float(H1), e1.y - __high2float(H1)));
            pl0[nt] = *(uint32_t*)&L0;
            pl1[nt] = *(uint32_t*)&L1;
        }
        s0 += __shfl_xor_sync(0xffffffffu, s0, 1);
        s0 += __shfl_xor_sync(0xffffffffu, s0, 2);
        s1 += __shfl_xor_sync(0xffffffffu, s1, 1);
        s1 += __shfl_xor_sync(0xffffffffu, s1, 2);
        l0r = l0r * c0 + s0;
        l1r = l1r * c1 + s1;
#pragma unroll
        for (int nt = 0; nt < 8; nt++) {
            O[nt][0] *= c0; O[nt][1] *= c0;
            O[nt][2] *= c1; O[nt][3] *= c1;
        }

        // ---- O += P V (2-term) ----
#pragma unroll
        for (int ks = 0; ks < 4; ks++) {
            int k0 = ks * 16;
            uint32_t aPh[4] = {ph0[2 * ks], ph1[2 * ks], ph0[2 * ks + 1], ph1[2 * ks + 1]};
            uint32_t aPl[4] = {pl0[2 * ks], pl1[2 * ks], pl0[2 * ks + 1], pl1[2 * ks + 1]};
#pragma unroll
            for (int jn = 0; jn < 4; jn++) {
                int n0 = jn * 16;
                uint32_t voff = (k0 + ((lane >> 3) & 1) * 8 + (lane & 7)) * 144
                              + (n0 + (lane >> 4) * 8) * 2;
                uint32_t vH[4];
                ldsm_x4_t(vH[0], vH[1], vH[2], vH[3], svh + voff);
                mma16816(O[2 * jn],     aPh, &vH[0]);
                mma16816(O[2 * jn + 1], aPh, &vH[2]);
                mma16816(O[2 * jn],     aPl, &vH[0]);
                mma16816(O[2 * jn + 1], aPl, &vH[2]);
            }
        }
    }

    // ---- epilogue ----
    float inv0 = 1.0f / l0r, inv1 = 1.0f / l1r;
    int r0 = q0 + m0 + (lane >> 2), r1 = r0 + 8;
#pragma unroll
    for (int nt = 0; nt < 8; nt++) {
        int col = h * HD + nt * 8 + (lane & 3) * 2;
        *(float2*)&g_att[(size_t)(b * P + r0) * D + col] =
            make_float2(O[nt][0] * inv0, O[nt][1] * inv0);
        *(float2*)&g_att[(size_t)(b * P + r1) * D + col] =
            make_float2(O[nt][2] * inv1, O[nt][3] * inv1);
    }
}

// =========================================================================
// Final LayerNorm over D=768, emits split fp16 for the output GEMM.
// =========================================================================
__global__ __launch_bounds__(256) void ln_final(
    const float* __restrict__ sc, const float* __restrict__ bi)
{
    __shared__ float red[8];
    int t = blockIdx.x;
    int tid = threadIdx.x;
    const float* x = g_att + (size_t)t * D;

    float v0 = x[tid], v1 = x[tid + 256], v2 = x[tid + 512];
    float s = v0 + v1 + v2;
#pragma unroll
    for (int o = 16; o; o >>= 1) s += __shfl_xor_sync(0xffffffffu, s, o);
    if ((tid & 31) == 0) red[tid >> 5] = s;
    __syncthreads();
    float tot = 0.f;
#pragma unroll
    for (int w = 0; w < 8; w++) tot += red[w];
    float mean = tot * (1.0f / 768.0f);

    float d0 = v0 - mean, d1 = v1 - mean, d2 = v2 - mean;
    float vv = d0 * d0 + d1 * d1 + d2 * d2;
#pragma unroll
    for (int o = 16; o; o >>= 1) vv += __shfl_xor_sync(0xffffffffu, vv, o);
    __syncthreads();
    if ((tid & 31) == 0) red[tid >> 5] = vv;
    __syncthreads();
    float vt = 0.f;
#pragma unroll
    for (int w = 0; w < 8; w++) vt += red[w];
    float inv = rsqrtf(vt * (1.0f / 768.0f) + EPS);

#pragma unroll
    for (int j = 0; j < 3; j++) {
        int idx = tid + j * 256;
        float dj = (j == 0 ? d0 : (j == 1 ? d1 : d2));
        float y = dj * inv * sc[idx] + bi[idx];
        __half hh = __float2half_rn(y);
        size_t o = (size_t)t * D + idx;
        g_a2h[o] = hh;
        g_a2l[o] = __float2half_rn(y - __half2float(hh));
    }
}

// =========================================================================
extern "C" void kernel_launch(void* const* d_in, const int* in_sizes, int n_in,
                              void* d_out, int out_size)
{
    const float* x       = (const float*)d_in[0];
    const float* Wqkv    = (const float*)d_in[1];
    const float* q_scale = (const float*)d_in[2];
    const float* q_bias  = (const float*)d_in[3];
    const float* k_scale = (const float*)d_in[4];
    const float* k_bias  = (const float*)d_in[5];
    const float* o_scale = (const float*)d_in[6];
    const float* o_bias  = (const float*)d_in[7];
    const float* Wout    = (const float*)d_in[8];
    const float* bout    = (const float*)d_in[9];
    float* out = (float*)d_out;

    __half *p_xh, *p_xl, *p_wqh, *p_woh, *p_a2h, *p_a2l;
    cudaGetSymbolAddress((void**)&p_xh, g_xh);
    cudaGetSymbolAddress((void**)&p_xl, g_xl);
    cudaGetSymbolAddress((void**)&p_wqh, g_wqh);
    cudaGetSymbolAddress((void**)&p_woh, g_woh);
    cudaGetSymbolAddress((void**)&p_a2h, g_a2h);
    cudaGetSymbolAddress((void**)&p_a2l, g_a2l);

    cudaFuncSetAttribute(gemm_mma<0>, cudaFuncAttributeMaxDynamicSharedMemorySize, GEMM_SMEM);
    cudaFuncSetAttribute(gemm_mma<1>, cudaFuncAttributeMaxDynamicSharedMemorySize, GEMM_SMEM);
    cudaFuncSetAttribute(attn_mma, cudaFuncAttributeMaxDynamicSharedMemorySize, ATT_SMEM);

    // 0) split x into fp16 hi/lo; transpose weights to single fp16
    conv_split<<<(TOK * D / 4 + 255) / 256, 256>>>(x, p_xh, p_xl, TOK * D / 4);
    conv_wT<<<dim3(QKVN / 32, D / 32), dim3(32, 8)>>>(Wqkv, p_wqh, D, QKVN);
    conv_wT<<<dim3(D / 32, D / 32), dim3(32, 8)>>>(Wout, p_woh, D, D);

    // 1) QKV projection with fused per-head LN + split epilogue
    gemm_mma<1><<<dim3(QKVN / 128, TOK / 128), 256, GEMM_SMEM>>>(
        p_xh, p_xl, p_wqh, nullptr, nullptr, TOK, QKVN, D,
        q_scale, q_bias, k_scale, k_bias);

    // 2) flash attention (fp16 2-term, Q-in-regs, double-buffered KV)
    attn_mma<<<dim3(B * H, P / 128), 256, ATT_SMEM>>>();

    // 3) final LN over D (emits split fp16)
    ln_final<<<TOK, 256>>>(o_scale, o_bias);

    // 4) output projection with bias
    gemm_mma<0><<<dim3(D / 128, TOK / 128), 256, GEMM_SMEM>>>(
        p_a2h, p_a2l, p_woh, bout, out, TOK, D, D,
        nullptr, nullptr, nullptr, nullptr);
}

// round 16
// speedup vs baseline: 1.6083x; 1.1570x over previous
#include <cuda_runtime.h>
#include <cuda_fp16.h>
#include <cstdint>
#include <math.h>

#define EPS 1e-6f
constexpr int B = 2, P = 2048, D = 768, H = 12, HD = 64;
constexpr int TOK = B * P;        // 4096
constexpr int QKVN = 3 * D;       // 2304

// ---------------- scratch (static device globals; no allocation) ----------------
__device__ float g_att[TOK * D];          // attention output, token-major

// split-fp16 operands (A-side split hi/lo, B-side single)
__device__ __half g_xh[TOK * D];
__device__ __half g_xl[TOK * D];
__device__ __half g_wqh[QKVN * D];        // W_qkv^T single fp16 [2304][768]
__device__ __half g_woh[D * D];           // W_out^T single fp16
__device__ __half g_a2h[TOK * D];         // ln_final out (single fp16)
// attention operands, [bh][p][hd]
__device__ __half g_qh[B * H * P * HD];   // q split hi
__device__ __half g_ql[B * H * P * HD];   // q split lo
__device__ __half g_kh[B * H * P * HD];   // k single
__device__ __half g_vh[B * H * P * HD];   // v single

// ======================= base-target PTX helpers =======================
__device__ __forceinline__ uint32_t smem_u32(const void* p) {
    uint32_t a;
    asm("{ .reg .u64 t; cvta.to.shared.u64 t, %1; cvt.u32.u64 %0, t; }" : "=r"(a) : "l"(p));
    return a;
}
#define CP_ASYNC16(dst, src) \
    asm volatile("cp.async.cg.shared.global [%0], [%1], 16;" :: "r"(dst), "l"(src))
#define CP_COMMIT() asm volatile("cp.async.commit_group;" ::: "memory")
#define CP_WAIT0()  asm volatile("cp.async.wait_group 0;" ::: "memory")

__device__ __forceinline__ void ldsm_x4(uint32_t& r0, uint32_t& r1, uint32_t& r2,
                                        uint32_t& r3, uint32_t addr) {
    asm volatile("ldmatrix.sync.aligned.m8n8.x4.shared.b16 {%0,%1,%2,%3}, [%4];"
                 : "=r"(r0), "=r"(r1), "=r"(r2), "=r"(r3) : "r"(addr));
}
__device__ __forceinline__ void ldsm_x4_t(uint32_t& r0, uint32_t& r1, uint32_t& r2,
                                          uint32_t& r3, uint32_t addr) {
    asm volatile("ldmatrix.sync.aligned.m8n8.x4.trans.shared.b16 {%0,%1,%2,%3}, [%4];"
                 : "=r"(r0), "=r"(r1), "=r"(r2), "=r"(r3) : "r"(addr));
}
__device__ __forceinline__ void mma16816(float* c, const uint32_t* a, const uint32_t* b) {
    asm volatile(
        "mma.sync.aligned.m16n8k16.row.col.f32.f16.f16.f32 "
        "{%0,%1,%2,%3}, {%4,%5,%6,%7}, {%8,%9}, {%0,%1,%2,%3};"
        : "+f"(c[0]), "+f"(c[1]), "+f"(c[2]), "+f"(c[3])
        : "r"(a[0]), "r"(a[1]), "r"(a[2]), "r"(a[3]), "r"(b[0]), "r"(b[1]));
}

// =========================================================================
// Split fp32 -> fp16 hi/lo, same layout.
// =========================================================================
__global__ __launch_bounds__(256) void conv_split(
    const float* __restrict__ src, __half* __restrict__ hi,
    __half* __restrict__ lo, int n4)
{
    int i = blockIdx.x * blockDim.x + threadIdx.x;
    if (i >= n4) return;
    float4 v = ((const float4*)src)[i];
    __half h0 = __float2half_rn(v.x), h1 = __float2half_rn(v.y);
    __half h2 = __float2half_rn(v.z), h3 = __float2half_rn(v.w);
    __half2* hp = (__half2*)hi;
    __half2* lp = (__half2*)lo;
    hp[2 * i] = __half2(h0, h1);
    hp[2 * i + 1] = __half2(h2, h3);
    lp[2 * i] = __half2(__float2half_rn(v.x - __half2float(h0)),
                        __float2half_rn(v.y - __half2float(h1)));
    lp[2 * i + 1] = __half2(__float2half_rn(v.z - __half2float(h2)),
                            __float2half_rn(v.w - __half2float(h3)));
}

// =========================================================================
// Transpose: W[K][N] f32 -> T[N][K] single fp16.  32x32 tiles.
// =========================================================================
__global__ __launch_bounds__(256) void conv_wT(
    const float* __restrict__ W, __half* __restrict__ Th, int K, int N)
{
    __shared__ float tile[32][33];
    int n0 = blockIdx.x * 32, k0 = blockIdx.y * 32;
    int tx = threadIdx.x, ty = threadIdx.y;
#pragma unroll
    for (int j = 0; j < 4; j++)
        tile[ty + 8 * j][tx] = W[(size_t)(k0 + ty + 8 * j) * N + n0 + tx];
    __syncthreads();
#pragma unroll
    for (int j = 0; j < 4; j++)
        Th[(size_t)(n0 + ty + 8 * j) * K + k0 + tx] =
            __float2half_rn(tile[tx][ty + 8 * j]);
}

// =========================================================================
// HMMA fp16 GEMM: C = Ah@Bh^T (+ Al@Bh^T if TERMS==2) (+bias), fp32 accum.
// MODE 0: plain epilogue.  MODE 1: fused QKV epilogue.
// 128x128 CTA tile, 8 warps, KC=32, double-buffered cp.async.
// =========================================================================
constexpr int TILE_B2 = 128 * 80;        // 10240 bytes per tile
constexpr int BUF_B2 = 3 * TILE_B2;      // Ah, Al, Bh slots
constexpr int GEMM_SMEM = 2 * BUF_B2;    // 61440

template<int MODE, int TERMS>
__global__ __launch_bounds__(256, 2) void gemm_mma(
    const __half* __restrict__ Ah, const __half* __restrict__ Al,
    const __half* __restrict__ Bh,
    const float* __restrict__ bias, float* __restrict__ C, int M, int N, int K,
    const float* __restrict__ qs, const float* __restrict__ qb,
    const float* __restrict__ ks, const float* __restrict__ kb)
{
    extern __shared__ char sm[];
    uint32_t sbase = smem_u32(sm);
    int tid = threadIdx.x, lane = tid & 31, wid = tid >> 5;
    int bm = blockIdx.y * 128, bn = blockIdx.x * 128;
    int m0 = (wid >> 2) * 64, n0 = (wid & 3) * 32;

    const int nch = K / 32;

    auto issue_load = [&](int c, int buf) {
        const __half* Ahp = Ah + (size_t)bm * K + c * 32;
        const __half* Bhp = Bh + (size_t)bn * K + c * 32;
        uint32_t base = sbase + buf * BUF_B2;
#pragma unroll
        for (int i = 0; i < 2; i++) {
            int u = tid + i * 256;       // 0..511
            int row = u >> 2, cc = u & 3;
            uint32_t so = row * 80 + cc * 16;
            size_t go = (size_t)row * K + cc * 8;
            CP_ASYNC16(base + so,               Ahp + go);
            if (TERMS == 2)
                CP_ASYNC16(base + TILE_B2 + so, Al + (size_t)bm * K + c * 32 + go);
            CP_ASYNC16(base + 2 * TILE_B2 + so, Bhp + go);
        }
        CP_COMMIT();
    };

    float acc[4][4][4];
#pragma unroll
    for (int mt = 0; mt < 4; mt++)
#pragma unroll
        for (int nt = 0; nt < 4; nt++)
#pragma unroll
            for (int j = 0; j < 4; j++) acc[mt][nt][j] = 0.f;

    issue_load(0, 0);
    for (int c = 0; c < nch; c++) {
        CP_WAIT0();
        __syncthreads();
        if (c + 1 < nch) issue_load(c + 1, (c + 1) & 1);

        uint32_t as  = sbase + (c & 1) * BUF_B2;
        uint32_t als = as + TILE_B2;
        uint32_t bs  = as + 2 * TILE_B2;
#pragma unroll
        for (int ks_ = 0; ks_ < 2; ks_++) {
            int k0 = ks_ * 16;
            uint32_t arow = (m0 + (lane & 15)) * 80 + (k0 + (lane >> 4) * 8) * 2;
            int nn = n0 + (lane >> 4) * 8 + (lane & 7);
            int kk = k0 + ((lane >> 3) & 1) * 8;

            uint32_t aH[4][4];
#pragma unroll
            for (int mt = 0; mt < 4; mt++)
                ldsm_x4(aH[mt][0], aH[mt][1], aH[mt][2], aH[mt][3],
                        as + arow + mt * 16 * 80);
            uint32_t bH[4][2];
#pragma unroll
            for (int p = 0; p < 2; p++) {
                uint32_t r0, r1, r2, r3;
                ldsm_x4(r0, r1, r2, r3, bs + (nn + p * 16) * 80 + kk * 2);
                bH[2 * p][0] = r0; bH[2 * p][1] = r1;
                bH[2 * p + 1][0] = r2; bH[2 * p + 1][1] = r3;
            }
#pragma unroll
            for (int mt = 0; mt < 4; mt++)
#pragma unroll
                for (int nt = 0; nt < 4; nt++)
                    mma16816(acc[mt][nt], aH[mt], bH[nt]);

            if (TERMS == 2) {
                uint32_t aL[4][4];
#pragma unroll
                for (int mt = 0; mt < 4; mt++)
                    ldsm_x4(aL[mt][0], aL[mt][1], aL[mt][2], aL[mt][3],
                            als + arow + mt * 16 * 80);
#pragma unroll
                for (int mt = 0; mt < 4; mt++)
#pragma unroll
                    for (int nt = 0; nt < 4; nt++)
                        mma16816(acc[mt][nt], aL[mt], bH[nt]);
            }
        }
    }

    int g = lane >> 2, q4 = lane & 3;

    if (MODE == 0) {
        int t2 = q4 * 2;
#pragma unroll
        for (int mt = 0; mt < 4; mt++) {
            int row = bm + m0 + mt * 16 + g;
#pragma unroll
            for (int nt = 0; nt < 4; nt++) {
                int col = bn + n0 + nt * 8 + t2;
                float bx = 0.f, by = 0.f;
                if (bias) { bx = bias[col]; by = bias[col + 1]; }
                float2 lo = make_float2(acc[mt][nt][0] + bx, acc[mt][nt][1] + by);
                float2 hi = make_float2(acc[mt][nt][2] + bx, acc[mt][nt][3] + by);
                *(float2*)&C[(size_t)row * N + col] = lo;
                *(float2*)&C[(size_t)(row + 8) * N + col] = hi;
            }
        }
    } else {
        // ---------- fused QKV epilogue ----------
        __syncthreads();                 // mainloop smem reads fully done
        float* red = (float*)sm;         // [128 rows][8 warps], +1024 for sumsq
        int sec = bn / D;                // 0=q, 1=k, 2=v
        int head = ((bn - sec * D) >> 6) + ((wid & 3) >> 1);

        float mean_[4][2], inv_[4][2];
        if (sec < 2) {
#pragma unroll
            for (int mt = 0; mt < 4; mt++) {
                float s0 = 0.f, s1 = 0.f, sq0 = 0.f, sq1 = 0.f;
#pragma unroll
                for (int nt = 0; nt < 4; nt++) {
                    float a0 = acc[mt][nt][0], a1 = acc[mt][nt][1];
                    float a2 = acc[mt][nt][2], a3 = acc[mt][nt][3];
                    s0 += a0 + a1;  sq0 += a0 * a0 + a1 * a1;
                    s1 += a2 + a3;  sq1 += a2 * a2 + a3 * a3;
                }
                s0 += __shfl_xor_sync(0xffffffffu, s0, 1);
                s0 += __shfl_xor_sync(0xffffffffu, s0, 2);
                s1 += __shfl_xor_sync(0xffffffffu, s1, 1);
                s1 += __shfl_xor_sync(0xffffffffu, s1, 2);
                sq0 += __shfl_xor_sync(0xffffffffu, sq0, 1);
                sq0 += __shfl_xor_sync(0xffffffffu, sq0, 2);
                sq1 += __shfl_xor_sync(0xffffffffu, sq1, 1);
                sq1 += __shfl_xor_sync(0xffffffffu, sq1, 2);
                if (q4 == 0) {
                    int r0 = m0 + mt * 16 + g;
                    red[r0 * 8 + wid] = s0;
                    red[1024 + r0 * 8 + wid] = sq0;
                    red[(r0 + 8) * 8 + wid] = s1;
                    red[1024 + (r0 + 8) * 8 + wid] = sq1;
                }
            }
            __syncthreads();
#pragma unroll
            for (int mt = 0; mt < 4; mt++)
#pragma unroll
                for (int rp = 0; rp < 2; rp++) {
                    int r = m0 + mt * 16 + g + rp * 8;
                    float S = red[r * 8 + wid] + red[r * 8 + (wid ^ 1)];
                    float Q = red[1024 + r * 8 + wid] + red[1024 + r * 8 + (wid ^ 1)];
                    float mn = S * (1.0f / 64.0f);
                    mean_[mt][rp] = mn;
                    inv_[mt][rp] = rsqrtf(Q * (1.0f / 64.0f) - mn * mn + EPS);
                }
        }

        const float* sc = (sec == 0) ? qs : ks;
        const float* bi = (sec == 0) ? qb : kb;
        float mul = (sec == 0) ? 0.125f : 1.0f;

#pragma unroll
        for (int mt = 0; mt < 4; mt++)
#pragma unroll
            for (int rp = 0; rp < 2; rp++) {
                int r = m0 + mt * 16 + g + rp * 8;
                int tok = bm + r;
                int b_ = tok >> 11, p_ = tok & 2047;
                size_t base = ((size_t)(b_ * H + head) * P + p_) * HD;
#pragma unroll
                for (int nt = 0; nt < 4; nt++) {
                    int cih = (n0 & 63) + nt * 8 + q4 * 2;
                    float v0 = acc[mt][nt][rp * 2];
                    float v1 = acc[mt][nt][rp * 2 + 1];
                    if (sec == 2) {
                        *(__half2*)&g_vh[base + cih] =
                            __float22half2_rn(make_float2(v0, v1));
                    } else {
                        float mn = mean_[mt][rp], iv = inv_[mt][rp];
                        float y0 = ((v0 - mn) * iv * sc[cih]     + bi[cih])     * mul;
                        float y1 = ((v1 - mn) * iv * sc[cih + 1] + bi[cih + 1]) * mul;
                        if (sec == 1) {
                            *(__half2*)&g_kh[base + cih] =
                                __float22half2_rn(make_float2(y0, y1));
                        } else {
                            __half2 Hh = __float22half2_rn(make_float2(y0, y1));
                            __half2 Ll = __float22half2_rn(
                                make_float2(y0 - __low2float(Hh),
                                            y1 - __high2float(Hh)));
                            *(__half2*)&g_qh[base + cih] = Hh;
                            *(__half2*)&g_ql[base + cih] = Ll;
                        }
                    }
                }
            }
    }
}

// =========================================================================
// Flash attention, fp16: S = Qh K^T + Ql K^T (2-term);  O += Ph V (1-term).
// Q fragments register-resident; KV double buffer overlaying dead Q smem.
// grid (B*H, P/128), 256 threads = 8 warps; warp w owns q rows w*16..+15.
// =========================================================================
constexpr int KVBUF = 18432;                 // kh, vh each 9216 B
constexpr int ATT_SMEM = 36864 + KVBUF;      // Q(hi+lo) staging + buf0 = 55296

__global__ __launch_bounds__(256, 2) void attn_mma()
{
    extern __shared__ char sm[];
    uint32_t sb = smem_u32(sm);

    int bh = blockIdx.x, q0 = blockIdx.y * 128;
    int b = bh / H, h = bh - b * H;
    int tid = threadIdx.x, lane = tid & 31, w = tid >> 5;
    const int m0 = w * 16;
    const int NKB = P / 64;

    // Q staged transiently at [0, 36864); buf1 will overlay it later.
    const uint32_t sqh = sb, sql = sb + 18432;
    size_t qbase = ((size_t)bh * P + q0) * HD;
#pragma unroll
    for (int i = 0; i < 4; i++) {
        int u = tid + i * 256;
        int row = u >> 3, c = u & 7;
        CP_ASYNC16(sqh + row * 144 + c * 16, g_qh + qbase + (size_t)row * HD + c * 8);
        CP_ASYNC16(sql + row * 144 + c * 16, g_ql + qbase + (size_t)row * HD + c * 8);
    }

    auto kv_issue = [&](int kb, uint32_t kbuf) {
        size_t kbase = ((size_t)bh * P + kb * 64) * HD;
#pragma unroll
        for (int i = 0; i < 2; i++) {
            int u = tid + i * 256;
            int row = u >> 3, c = u & 7;
            uint32_t so = row * 144 + c * 16;
            size_t go = (size_t)row * HD + c * 8;
            CP_ASYNC16(kbuf + so,        g_kh + kbase + go);
            CP_ASYNC16(kbuf + 9216 + so, g_vh + kbase + go);
        }
        CP_COMMIT();
    };

    kv_issue(0, sb + 36864);    // buf0 beyond Q region
    CP_WAIT0();
    __syncthreads();

    uint32_t qaH[4][4], qaL[4][4];
#pragma unroll
    for (int ks = 0; ks < 4; ks++) {
        uint32_t qoff = (m0 + (lane & 15)) * 144 + (ks * 16 + (lane >> 4) * 8) * 2;
        ldsm_x4(qaH[ks][0], qaH[ks][1], qaH[ks][2], qaH[ks][3], sqh + qoff);
        ldsm_x4(qaL[ks][0], qaL[ks][1], qaL[ks][2], qaL[ks][3], sql + qoff);
    }
    __syncthreads();   // all warps done reading Q smem before buf1 overlays it
    kv_issue(1, sb);   // buf1 = start of old Q region

    float m0r = -1e30f, m1r = -1e30f, l0r = 0.f, l1r = 0.f;
    float O[8][4];
#pragma unroll
    for (int nt = 0; nt < 8; nt++)
#pragma unroll
        for (int j = 0; j < 4; j++) O[nt][j] = 0.f;

    for (int kb = 0; kb < NKB; kb++) {
        if (kb > 0) {
            CP_WAIT0();
            __syncthreads();
            if (kb + 1 < NKB)
                kv_issue(kb + 1, ((kb + 1) & 1) ? sb : sb + 36864);
        }
        uint32_t kbuf = (kb & 1) ? sb : sb + 36864;
        uint32_t skh = kbuf, svh = kbuf + 9216;

        // ---- S = Q K^T (2-term, Q from registers) ----
        float sa[8][4];
#pragma unroll
        for (int nt = 0; nt < 8; nt++)
#pragma unroll
            for (int j = 0; j < 4; j++) sa[nt][j] = 0.f;

#pragma unroll
        for (int ks = 0; ks < 4; ks++) {
            int k0 = ks * 16;
#pragma unroll
            for (int j = 0; j < 4; j++) {
                int n0 = j * 16;
                uint32_t koff = (n0 + (lane >> 4) * 8 + (lane & 7)) * 144
                              + (k0 + ((lane >> 3) & 1) * 8) * 2;
                uint32_t bH[4];
                ldsm_x4(bH[0], bH[1], bH[2], bH[3], skh + koff);
                mma16816(sa[2 * j],     qaH[ks], &bH[0]);
                mma16816(sa[2 * j + 1], qaH[ks], &bH[2]);
                mma16816(sa[2 * j],     qaL[ks], &bH[0]);
                mma16816(sa[2 * j + 1], qaL[ks], &bH[2]);
            }
        }

        // ---- online softmax ----
        float mx0 = -1e30f, mx1 = -1e30f;
#pragma unroll
        for (int nt = 0; nt < 8; nt++) {
            mx0 = fmaxf(mx0, fmaxf(sa[nt][0], sa[nt][1]));
            mx1 = fmaxf(mx1, fmaxf(sa[nt][2], sa[nt][3]));
        }
        mx0 = fmaxf(mx0, __shfl_xor_sync(0xffffffffu, mx0, 1));
        mx0 = fmaxf(mx0, __shfl_xor_sync(0xffffffffu, mx0, 2));
        mx1 = fmaxf(mx1, __shfl_xor_sync(0xffffffffu, mx1, 1));
        mx1 = fmaxf(mx1, __shfl_xor_sync(0xffffffffu, mx1, 2));
        float mn0 = fmaxf(m0r, mx0), mn1 = fmaxf(m1r, mx1);
        float c0 = __expf(m0r - mn0), c1 = __expf(m1r - mn1);
        m0r = mn0; m1r = mn1;

        float s0 = 0.f, s1 = 0.f;
        uint32_t ph0[8], ph1[8];
#pragma unroll
        for (int nt = 0; nt < 8; nt++) {
            float2 e0 = make_float2(__expf(sa[nt][0] - mn0), __expf(sa[nt][1] - mn0));
            float2 e1 = make_float2(__expf(sa[nt][2] - mn1), __expf(sa[nt][3] - mn1));
            s0 += e0.x + e0.y;
            s1 += e1.x + e1.y;
            __half2 H0 = __float22half2_rn(e0);
            __half2 H1 = __float22half2_rn(e1);
            ph0[nt] = *(uint32_t*)&H0;
            ph1[nt] = *(uint32_t*)&H1;
        }
        s0 += __shfl_xor_sync(0xffffffffu, s0, 1);
        s0 += __shfl_xor_sync(0xffffffffu, s0, 2);
        s1 += __shfl_xor_sync(0xffffffffu, s1, 1);
        s1 += __shfl_xor_sync(0xffffffffu, s1, 2);
        l0r = l0r * c0 + s0;
        l1r = l1r * c1 + s1;
#pragma unroll
        for (int nt = 0; nt < 8; nt++) {
            O[nt][0] *= c0; O[nt][1] *= c0;
            O[nt][2] *= c1; O[nt][3] *= c1;
        }

        // ---- O += P V (1-term) ----
#pragma unroll
        for (int ks = 0; ks < 4; ks++) {
            int k0 = ks * 16;
            uint32_t aPh[4] = {ph0[2 * ks], ph1[2 * ks], ph0[2 * ks + 1], ph1[2 * ks + 1]};
#pragma unroll
            for (int jn = 0; jn < 4; jn++) {
                int n0 = jn * 16;
                uint32_t voff = (k0 + ((lane >> 3) & 1) * 8 + (lane & 7)) * 144
                              + (n0 + (lane >> 4) * 8) * 2;
                uint32_t vH[4];
                ldsm_x4_t(vH[0], vH[1], vH[2], vH[3], svh + voff);
                mma16816(O[2 * jn],     aPh, &vH[0]);
                mma16816(O[2 * jn + 1], aPh, &vH[2]);
            }
        }
    }

    // ---- epilogue ----
    float inv0 = 1.0f / l0r, inv1 = 1.0f / l1r;
    int r0 = q0 + m0 + (lane >> 2), r1 = r0 + 8;
#pragma unroll
    for (int nt = 0; nt < 8; nt++) {
        int col = h * HD + nt * 8 + (lane & 3) * 2;
        *(float2*)&g_att[(size_t)(b * P + r0) * D + col] =
            make_float2(O[nt][0] * inv0, O[nt][1] * inv0);
        *(float2*)&g_att[(size_t)(b * P + r1) * D + col] =
            make_float2(O[nt][2] * inv1, O[nt][3] * inv1);
    }
}

// =========================================================================
// Final LayerNorm over D=768, emits single fp16 for the output GEMM.
// =========================================================================
__global__ __launch_bounds__(256) void ln_final(
    const float* __restrict__ sc, const float* __restrict__ bi)
{
    __shared__ float red[8];
    int t = blockIdx.x;
    int tid = threadIdx.x;
    const float* x = g_att + (size_t)t * D;

    float v0 = x[tid], v1 = x[tid + 256], v2 = x[tid + 512];
    float s = v0 + v1 + v2;
#pragma unroll
    for (int o = 16; o; o >>= 1) s += __shfl_xor_sync(0xffffffffu, s, o);
    if ((tid & 31) == 0) red[tid >> 5] = s;
    __syncthreads();
    float tot = 0.f;
#pragma unroll
    for (int w = 0; w < 8; w++) tot += red[w];
    float mean = tot * (1.0f / 768.0f);

    float d0 = v0 - mean, d1 = v1 - mean, d2 = v2 - mean;
    float vv = d0 * d0 + d1 * d1 + d2 * d2;
#pragma unroll
    for (int o = 16; o; o >>= 1) vv += __shfl_xor_sync(0xffffffffu, vv, o);
    __syncthreads();
    if ((tid & 31) == 0) red[tid >> 5] = vv;
    __syncthreads();
    float vt = 0.f;
#pragma unroll
    for (int w = 0; w < 8; w++) vt += red[w];
    float inv = rsqrtf(vt * (1.0f / 768.0f) + EPS);

#pragma unroll
    for (int j = 0; j < 3; j++) {
        int idx = tid + j * 256;
        float dj = (j == 0 ? d0 : (j == 1 ? d1 : d2));
        float y = dj * inv * sc[idx] + bi[idx];
        g_a2h[(size_t)t * D + idx] = __float2half_rn(y);
    }
}

// =========================================================================
extern "C" void kernel_launch(void* const* d_in, const int* in_sizes, int n_in,
                              void* d_out, int out_size)
{
    const float* x       = (const float*)d_in[0];
    const float* Wqkv    = (const float*)d_in[1];
    const float* q_scale = (const float*)d_in[2];
    const float* q_bias  = (const float*)d_in[3];
    const float* k_scale = (const float*)d_in[4];
    const float* k_bias  = (const float*)d_in[5];
    const float* o_scale = (const float*)d_in[6];
    const float* o_bias  = (const float*)d_in[7];
    const float* Wout    = (const float*)d_in[8];
    const float* bout    = (const float*)d_in[9];
    float* out = (float*)d_out;

    __half *p_xh, *p_xl, *p_wqh, *p_woh, *p_a2h;
    cudaGetSymbolAddress((void**)&p_xh, g_xh);
    cudaGetSymbolAddress((void**)&p_xl, g_xl);
    cudaGetSymbolAddress((void**)&p_wqh, g_wqh);
    cudaGetSymbolAddress((void**)&p_woh, g_woh);
    cudaGetSymbolAddress((void**)&p_a2h, g_a2h);

    cudaFuncSetAttribute((const void*)gemm_mma<0, 1>,
                         cudaFuncAttributeMaxDynamicSharedMemorySize, GEMM_SMEM);
    cudaFuncSetAttribute((const void*)gemm_mma<1, 2>,
                         cudaFuncAttributeMaxDynamicSharedMemorySize, GEMM_SMEM);
    cudaFuncSetAttribute(attn_mma, cudaFuncAttributeMaxDynamicSharedMemorySize, ATT_SMEM);

    // 0) split x into fp16 hi/lo; transpose weights to single fp16
    conv_split<<<(TOK * D / 4 + 255) / 256, 256>>>(x, p_xh, p_xl, TOK * D / 4);
    conv_wT<<<dim3(QKVN / 32, D / 32), dim3(32, 8)>>>(Wqkv, p_wqh, D, QKVN);
    conv_wT<<<dim3(D / 32, D / 32), dim3(32, 8)>>>(Wout, p_woh, D, D);

    // 1) QKV projection (2-term) with fused per-head LN + split epilogue
    gemm_mma<1, 2><<<dim3(QKVN / 128, TOK / 128), 256, GEMM_SMEM>>>(
        p_xh, p_xl, p_wqh, nullptr, nullptr, TOK, QKVN, D,
        q_scale, q_bias, k_scale, k_bias);

    // 2) flash attention (S 2-term, PV 1-term)
    attn_mma<<<dim3(B * H, P / 128), 256, ATT_SMEM>>>();

    // 3) final LN over D (emits single fp16)
    ln_final<<<TOK, 256>>>(o_scale, o_bias);

    // 4) output projection (1-term) with bias
    gemm_mma<0, 1><<<dim3(D / 128, TOK / 128), 256, GEMM_SMEM>>>(
        p_a2h, nullptr, p_woh, bout, out, TOK, D, D,
        nullptr, nullptr, nullptr, nullptr);
}